// round 3
// baseline (speedup 1.0000x reference)
#include <cuda_runtime.h>
#include <math_constants.h>

// SwinWindowAttention fused kernel, round 3:
// 512 threads/CTA (16 warps), column-partitioned GEMMs with transposed
// activations in SMEM so weight reads are broadcast LDS (no per-warp
// replication of weight traffic). Packed fma.rn.f32x2 throughout GEMMs.
// Shapes: 2048 windows; N=49; C=128; H=4; hd=32.

#define WIN_TOTAL 2048
#define NTOK 49
#define CDIM 128
#define NHEAD 4
#define HDIM 32
#define C3 384
#define QS 388        /* qkv smem row stride (floats): 388%32==4 -> conflict-free */
#define XTS 52        /* transposed activation row stride */
#define PSS 52        /* prob smem row stride */
#define THREADS 512

// shared memory (floats):
#define SM_XT   0                       /* xs_t[128][52] transposed x / attn-out : 6656 */
#define SM_QK   6656                    /* qkv output [49][388]                  : 19012 */
#define SM_WS   (6656 + 19012)          /* weight staging (qkv chunks, proj_w)   : 16384 */
#define SM_PS   (SM_WS + 16384)         /* probs [4*49][52]                      : 10192 */
#define SM_RELB (SM_PS + 10192)         /* rel table 169*4                       : 676  */
#define SM_MS   (SM_RELB + 676)         /* shift mask 49*49                      : 2401 */
#define SM_FLOATS (SM_MS + 2401)
#define SM_BYTES (SM_FLOATS * 4)        /* 221284 B */

typedef unsigned long long u64;

__device__ __forceinline__ void fma2(u64& d, u64 a, u64 b) {
    asm("fma.rn.f32x2 %0, %1, %2, %0;" : "+l"(d) : "l"(a), "l"(b));
}
__device__ __forceinline__ u64 bcast2(float x) {
    u64 r; asm("mov.b64 %0, {%1, %1};" : "=l"(r) : "f"(x)); return r;
}
__device__ __forceinline__ float2 unpack2(u64 v) {
    float2 r; asm("mov.b64 {%0, %1}, %2;" : "=f"(r.x), "=f"(r.y) : "l"(v)); return r;
}

__global__ __launch_bounds__(THREADS, 1)
void swin_win_attn_kernel(const float* __restrict__ xg_all,
                          const float* __restrict__ maskg,
                          const float* __restrict__ qkv_w,
                          const float* __restrict__ qkv_b,
                          const float* __restrict__ proj_w,
                          const float* __restrict__ proj_b,
                          const float* __restrict__ rel_table,
                          float* __restrict__ outg)
{
    extern __shared__ float sm[];
    float* xt   = sm + SM_XT;
    float* qk   = sm + SM_QK;
    float* ws   = sm + SM_WS;
    float* ps   = sm + SM_PS;
    float* relb = sm + SM_RELB;
    float* ms   = sm + SM_MS;

    const int tid  = threadIdx.x;
    const int warp = tid >> 5;
    const int lane = tid & 31;
    const int win  = blockIdx.x;
    const int nw   = win & 63;

    // ---- load input tile (transposed), rel table, shift mask ----
    {
        const float4* src = (const float4*)(xg_all + (size_t)win * (NTOK * CDIM));
        for (int idx = tid; idx < (NTOK * CDIM) / 4; idx += THREADS) {
            float4 v = src[idx];
            int i = (4 * idx) >> 7;          // token
            int c = (4 * idx) & 127;         // channel (multiple of 4)
            float* d = xt + c * XTS + i;
            d[0] = v.x; d[XTS] = v.y; d[2*XTS] = v.z; d[3*XTS] = v.w;
        }
        for (int i = tid; i < 676; i += THREADS) relb[i] = rel_table[i];
        const float* mgsrc = maskg + nw * (NTOK * NTOK);
        for (int i = tid; i < NTOK * NTOK; i += THREADS) ms[i] = mgsrc[i];
    }

    // ============ QKV GEMM: [49x128]@[128x384], column-partitioned ==========
    // warp owns cols [24w, 24w+24); lane owns rows (lane) and (lane+32 | dummy 48)
    const int colBase = 24 * warp;
    const int r0 = lane;
    const int r1 = (lane < 17) ? lane + 32 : 48;

    u64 acc0[12], acc1[12];
    #pragma unroll
    for (int j = 0; j < 12; ++j) { acc0[j] = 0ull; acc1[j] = 0ull; }

    for (int c = 0; c < 4; ++c) {
        __syncthreads();
        {   // stage 32 rows of qkv_w (3072 float4), 512 threads
            const float4* src = (const float4*)qkv_w + c * 3072;
            float4* dst = (float4*)ws;
            #pragma unroll
            for (int t = 0; t < 6; ++t) dst[tid + t * THREADS] = src[tid + t * THREADS];
        }
        __syncthreads();
        const int k0 = 32 * c;
        #pragma unroll 2
        for (int kk = 0; kk < 32; ++kk) {
            u64 w2[12];
            {
                const ulonglong2* p = (const ulonglong2*)(ws + kk * C3 + colBase);
                #pragma unroll
                for (int t = 0; t < 6; ++t) { ulonglong2 v = p[t]; w2[2*t] = v.x; w2[2*t+1] = v.y; }
            }
            const float* xcol = xt + (k0 + kk) * XTS;
            u64 bx0 = bcast2(xcol[r0]);
            u64 bx1 = bcast2(xcol[r1]);
            #pragma unroll
            for (int j = 0; j < 12; ++j) { fma2(acc0[j], bx0, w2[j]); fma2(acc1[j], bx1, w2[j]); }
        }
    }
    {   // write qkv (+bias) rows
        const float4* b4 = (const float4*)(qkv_b + colBase);
        float bb[24];
        #pragma unroll
        for (int t = 0; t < 6; ++t) { float4 v = b4[t]; bb[4*t]=v.x; bb[4*t+1]=v.y; bb[4*t+2]=v.z; bb[4*t+3]=v.w; }
        float4* d0 = (float4*)(qk + r0 * QS + colBase);
        #pragma unroll
        for (int t = 0; t < 6; ++t) {
            float2 a = unpack2(acc0[2*t]), b = unpack2(acc0[2*t+1]);
            d0[t] = make_float4(a.x+bb[4*t], a.y+bb[4*t+1], b.x+bb[4*t+2], b.y+bb[4*t+3]);
        }
        if (lane < 17) {
            float4* d1 = (float4*)(qk + r1 * QS + colBase);
            #pragma unroll
            for (int t = 0; t < 6; ++t) {
                float2 a = unpack2(acc1[2*t]), b = unpack2(acc1[2*t+1]);
                d1[t] = make_float4(a.x+bb[4*t], a.y+bb[4*t+1], b.x+bb[4*t+2], b.y+bb[4*t+3]);
            }
        }
    }
    __syncthreads();

    // stage proj_w into ws (4096 float4); consumed after the post-scores barrier
    {
        const float4* src = (const float4*)proj_w;
        float4* dst = (float4*)ws;
        #pragma unroll
        for (int t = 0; t < 8; ++t) dst[tid + t * THREADS] = src[tid + t * THREADS];
    }

    // ================= attention scores + softmax =================
    const float scale = 0.17677669529663687f;
    const float NEG_INF = -CUDART_INF_F;
    for (int m = warp; m < NHEAD * NTOK; m += 16) {
        const int h = m / NTOK;
        const int i = m - h * NTOK;
        u64 qr2[16];
        {
            const ulonglong2* q2 = (const ulonglong2*)(qk + i * QS + HDIM * h);
            #pragma unroll
            for (int d = 0; d < 8; ++d) { ulonglong2 t = q2[d]; qr2[2*d] = t.x; qr2[2*d+1] = t.y; }
        }
        const float* mrow = ms + i * NTOK;
        const int iy = i / 7, ix = i - 7 * (i / 7);

        float s0;
        {
            const int j = lane;
            const ulonglong2* k2 = (const ulonglong2*)(qk + j * QS + CDIM + HDIM * h);
            u64 da = 0ull, db = 0ull;
            #pragma unroll
            for (int d = 0; d < 8; ++d) {
                ulonglong2 t = k2[d];
                fma2(da, qr2[2*d], t.x);
                fma2(db, qr2[2*d+1], t.y);
            }
            float2 fa = unpack2(da), fb = unpack2(db);
            float dot = (fa.x + fa.y) + (fb.x + fb.y);
            const int jy = j / 7, jx = j - 7 * jy;
            s0 = fmaf(dot, scale, relb[((iy - jy + 6) * 13 + (ix - jx + 6)) * 4 + h] + mrow[j]);
        }
        float s1 = NEG_INF;
        if (lane < 17) {
            const int j = lane + 32;
            const ulonglong2* k2 = (const ulonglong2*)(qk + j * QS + CDIM + HDIM * h);
            u64 da = 0ull, db = 0ull;
            #pragma unroll
            for (int d = 0; d < 8; ++d) {
                ulonglong2 t = k2[d];
                fma2(da, qr2[2*d], t.x);
                fma2(db, qr2[2*d+1], t.y);
            }
            float2 fa = unpack2(da), fb = unpack2(db);
            float dot = (fa.x + fa.y) + (fb.x + fb.y);
            const int jy = j / 7, jx = j - 7 * jy;
            s1 = fmaf(dot, scale, relb[((iy - jy + 6) * 13 + (ix - jx + 6)) * 4 + h] + mrow[j]);
        }
        float mx = fmaxf(s0, s1);
        #pragma unroll
        for (int o = 16; o; o >>= 1) mx = fmaxf(mx, __shfl_xor_sync(0xffffffffu, mx, o));
        float e0 = __expf(s0 - mx);
        float e1 = (lane < 17) ? __expf(s1 - mx) : 0.f;
        float sum = e0 + e1;
        #pragma unroll
        for (int o = 16; o; o >>= 1) sum += __shfl_xor_sync(0xffffffffu, sum, o);
        const float inv = 1.0f / sum;
        float* pr = ps + (h * NTOK + i) * PSS;
        pr[lane] = e0 * inv;
        if (lane < 17) pr[lane + 32] = e1 * inv;
    }
    __syncthreads();

    // ================= attn @ V -> xt (transposed attn-out) =================
    // warp owns rows i = warp + 16r (r=0..3); lane owns col 32h+lane per head
    float av[4][4];
    #pragma unroll
    for (int r = 0; r < 4; ++r)
        #pragma unroll
        for (int h = 0; h < 4; ++h) av[r][h] = 0.f;

    for (int j = 0; j < 48; j += 4) {
        float vv[4][4];
        #pragma unroll
        for (int q = 0; q < 4; ++q)
            #pragma unroll
            for (int h = 0; h < 4; ++h)
                vv[q][h] = qk[(j + q) * QS + 2 * CDIM + HDIM * h + lane];
        #pragma unroll
        for (int r = 0; r < 4; ++r) {
            int i = warp + 16 * r; if (i > 48) i = 48;
            #pragma unroll
            for (int h = 0; h < 4; ++h) {
                float4 p4 = *(const float4*)(ps + (h * NTOK + i) * PSS + j);
                av[r][h] = fmaf(p4.x, vv[0][h], av[r][h]);
                av[r][h] = fmaf(p4.y, vv[1][h], av[r][h]);
                av[r][h] = fmaf(p4.z, vv[2][h], av[r][h]);
                av[r][h] = fmaf(p4.w, vv[3][h], av[r][h]);
            }
        }
    }
    {   // j = 48 remainder
        float vv[4];
        #pragma unroll
        for (int h = 0; h < 4; ++h) vv[h] = qk[48 * QS + 2 * CDIM + HDIM * h + lane];
        #pragma unroll
        for (int r = 0; r < 4; ++r) {
            int i = warp + 16 * r; if (i > 48) i = 48;
            #pragma unroll
            for (int h = 0; h < 4; ++h)
                av[r][h] = fmaf(ps[(h * NTOK + i) * PSS + 48], vv[h], av[r][h]);
        }
    }
    #pragma unroll
    for (int r = 0; r < 4; ++r) {
        int i = warp + 16 * r;
        if (i < NTOK) {
            #pragma unroll
            for (int h = 0; h < 4; ++h)
                xt[(HDIM * h + lane) * XTS + i] = av[r][h];   // transposed store
        }
    }
    __syncthreads();

    // ========== projection: [49x128]@[128x128], column-partitioned ==========
    // warp owns cols [8w, 8w+8); lane owns rows r0, r1
    const int pcol = 8 * warp;
    u64 pa0[4], pa1[4];
    #pragma unroll
    for (int j = 0; j < 4; ++j) { pa0[j] = 0ull; pa1[j] = 0ull; }

    #pragma unroll 4
    for (int k = 0; k < CDIM; ++k) {
        u64 w2[4];
        {
            const ulonglong2* p = (const ulonglong2*)(ws + k * CDIM + pcol);
            ulonglong2 a = p[0], b = p[1];
            w2[0]=a.x; w2[1]=a.y; w2[2]=b.x; w2[3]=b.y;
        }
        const float* acol = xt + k * XTS;
        u64 b0 = bcast2(acol[r0]);
        u64 b1 = bcast2(acol[r1]);
        #pragma unroll
        for (int j = 0; j < 4; ++j) { fma2(pa0[j], b0, w2[j]); fma2(pa1[j], b1, w2[j]); }
    }
    {
        const float4* pb4 = (const float4*)(proj_b + pcol);
        float4 B0 = pb4[0], B1 = pb4[1];
        float* og = outg + (size_t)win * (NTOK * CDIM);
        {
            float2 a = unpack2(pa0[0]), b = unpack2(pa0[1]);
            float2 c2 = unpack2(pa0[2]), d = unpack2(pa0[3]);
            float4* o4 = (float4*)(og + r0 * CDIM + pcol);
            o4[0] = make_float4(a.x+B0.x, a.y+B0.y, b.x+B0.z, b.y+B0.w);
            o4[1] = make_float4(c2.x+B1.x, c2.y+B1.y, d.x+B1.z, d.y+B1.w);
        }
        if (lane < 17) {
            float2 a = unpack2(pa1[0]), b = unpack2(pa1[1]);
            float2 c2 = unpack2(pa1[2]), d = unpack2(pa1[3]);
            float4* o4 = (float4*)(og + r1 * CDIM + pcol);
            o4[0] = make_float4(a.x+B0.x, a.y+B0.y, b.x+B0.z, b.y+B0.w);
            o4[1] = make_float4(c2.x+B1.x, c2.y+B1.y, d.x+B1.z, d.y+B1.w);
        }
    }
}

extern "C" void kernel_launch(void* const* d_in, const int* in_sizes, int n_in,
                              void* d_out, int out_size)
{
    const float* x      = (const float*)d_in[0];
    const float* mask   = (const float*)d_in[1];
    const float* qkv_w  = (const float*)d_in[2];
    const float* qkv_b  = (const float*)d_in[3];
    const float* proj_w = (const float*)d_in[4];
    const float* proj_b = (const float*)d_in[5];
    const float* relt   = (const float*)d_in[6];
    float* out = (float*)d_out;

    cudaFuncSetAttribute(swin_win_attn_kernel,
                         cudaFuncAttributeMaxDynamicSharedMemorySize, SM_BYTES);
    swin_win_attn_kernel<<<WIN_TOTAL, THREADS, SM_BYTES>>>(
        x, mask, qkv_w, qkv_b, proj_w, proj_b, relt, out);
}